// round 16
// baseline (speedup 1.0000x reference)
#include <cuda_runtime.h>

#define B_ROWS  32768
#define D_DIM   256
#define K_CODES 2048

// output layout (float32): quantized_st[B*D], vq_loss, entropy, inds[B], cluster_metric
#define OFF_VQ  8388608
#define OFF_ENT 8388609
#define OFF_IND 8388610
#define OFF_CL  8421378

#define BM 64
#define BN 128
#define DK 32
#define AS_STRIDE 68    // 32 floats padded: 16B-aligned rows, 4-way store conflicts max
#define BS_STRIDE 132

__device__ float g_xsq[B_ROWS];
__device__ float g_esq[K_CODES];
__device__ int   g_counts[K_CODES];
__device__ float g_cl_part[512];
__device__ unsigned int g_done;

__device__ __forceinline__ unsigned long long dup_f32(float f) {
    unsigned long long r;
    asm("mov.b64 %0, {%1, %1};" : "=l"(r) : "f"(f));
    return r;
}
__device__ __forceinline__ void ffma2(unsigned long long &d, unsigned long long a,
                                      unsigned long long b) {
    asm("fma.rn.f32x2 %0, %1, %2, %0;" : "+l"(d) : "l"(a), "l"(b));
}
__device__ __forceinline__ void unpack_f32x2(unsigned long long v, float &lo, float &hi) {
    asm("mov.b64 {%0, %1}, %2;" : "=f"(lo), "=f"(hi) : "l"(v));
}

// ---------------- prep: row norms (2 rows/warp) + zero histogram/counter ----------------
// Per-row arithmetic (load layout, square-sum order, shuffle tree) is bit-identical
// to the R1 version; two independent rows per warp only add ILP/MLP.
__global__ void vq_prep_kernel(const float* __restrict__ latents,
                               const float* __restrict__ embedding) {
    const int lane = threadIdx.x & 31;
    const int warp = threadIdx.x >> 5;
    const int gw0  = (blockIdx.x * 8 + warp) * 2;

#pragma unroll
    for (int rr = 0; rr < 2; rr++) {
        const int gw = gw0 + rr;
        const float* src = nullptr;
        float* dst = nullptr;
        int row = 0;
        if (gw < B_ROWS)                 { src = latents;   dst = g_xsq; row = gw; }
        else if (gw < B_ROWS + K_CODES)  { src = embedding; dst = g_esq; row = gw - B_ROWS; }
        if (!src) continue;

        const float4* p = reinterpret_cast<const float4*>(src + (size_t)row * D_DIM);
        float4 a = p[lane];
        float4 b = p[lane + 32];
        float s = a.x*a.x + a.y*a.y + a.z*a.z + a.w*a.w
                + b.x*b.x + b.y*b.y + b.z*b.z + b.w*b.w;
#pragma unroll
        for (int off = 16; off; off >>= 1)
            s += __shfl_down_sync(0xffffffffu, s, off);
        if (lane == 0) dst[row] = s;
    }

    if (blockIdx.x == 0) {
        for (int k = threadIdx.x; k < K_CODES; k += blockDim.x) g_counts[k] = 0;
        if (threadIdx.x == 0) g_done = 0;
    }
}

// ---------------- main: GEMM + argmin + gather/STE/hist + last-block finalize ----------------
__global__ void vq_argmin_kernel(const float* __restrict__ latents,
                                 const float* __restrict__ embedding,
                                 float* __restrict__ out) {
    __shared__ float As[DK * AS_STRIDE];   // [k][m] transposed
    __shared__ float Bs[DK * BS_STRIDE];   // [k][n] transposed
    __shared__ float s_esq[BN];
    __shared__ float s_xsq[BM];
    __shared__ float red_s[BM][17];
    __shared__ int   red_i[BM][17];
    __shared__ float s_cl[BM];
    __shared__ int   s_ind[BM];
    __shared__ bool  s_last;

    const int tid  = threadIdx.x;
    const int tx   = tid & 15;     // 16 col-groups of 8
    const int ty   = tid >> 4;     // 8 row-groups of 8
    const int row0 = blockIdx.x * BM;

    if (tid < BM) s_xsq[tid] = g_xsq[row0 + tid];

    float best_s[8];
    int   best_i[8];
#pragma unroll
    for (int i = 0; i < 8; i++) { best_s[i] = 3.0e38f; best_i[i] = 0; }

    const int ra = tid >> 3;   // 0..15
    const int ca = tid & 7;    // 0..7 (float4 group in D-chunk)

    for (int ct = 0; ct < K_CODES; ct += BN) {
        s_esq[tid] = g_esq[ct + tid];

        unsigned long long acc[4][8];
#pragma unroll
        for (int p = 0; p < 4; p++)
#pragma unroll
            for (int j = 0; j < 8; j++) acc[p][j] = 0ULL;

        for (int d0 = 0; d0 < D_DIM; d0 += DK) {
            __syncthreads();
            // A tile: 64 rows x 32 d, transposed store
#pragma unroll
            for (int s = 0; s < 4; s++) {
                const int r = ra + 16 * s;
                const float4 v = *reinterpret_cast<const float4*>(
                    latents + (size_t)(row0 + r) * D_DIM + d0 + 4 * ca);
                As[(4*ca + 0) * AS_STRIDE + r] = v.x;
                As[(4*ca + 1) * AS_STRIDE + r] = v.y;
                As[(4*ca + 2) * AS_STRIDE + r] = v.z;
                As[(4*ca + 3) * AS_STRIDE + r] = v.w;
            }
            // B tile: 128 codes x 32 d, transposed store
#pragma unroll
            for (int s = 0; s < 8; s++) {
                const int c = ra + 16 * s;
                const float4 v = *reinterpret_cast<const float4*>(
                    embedding + (size_t)(ct + c) * D_DIM + d0 + 4 * ca);
                Bs[(4*ca + 0) * BS_STRIDE + c] = v.x;
                Bs[(4*ca + 1) * BS_STRIDE + c] = v.y;
                Bs[(4*ca + 2) * BS_STRIDE + c] = v.z;
                Bs[(4*ca + 3) * BS_STRIDE + c] = v.w;
            }
            __syncthreads();

#pragma unroll
            for (int k = 0; k < DK; k++) {
                const ulonglong2 a01 = *reinterpret_cast<const ulonglong2*>(
                    &As[k * AS_STRIDE + ty * 8]);
                const ulonglong2 a23 = *reinterpret_cast<const ulonglong2*>(
                    &As[k * AS_STRIDE + ty * 8 + 4]);
                const float4 b0 = *reinterpret_cast<const float4*>(
                    &Bs[k * BS_STRIDE + tx * 8]);
                const float4 b1 = *reinterpret_cast<const float4*>(
                    &Bs[k * BS_STRIDE + tx * 8 + 4]);
                const float bf[8] = {b0.x, b0.y, b0.z, b0.w, b1.x, b1.y, b1.z, b1.w};
#pragma unroll
                for (int j = 0; j < 8; j++) {
                    const unsigned long long bd = dup_f32(bf[j]);
                    ffma2(acc[0][j], a01.x, bd);
                    ffma2(acc[1][j], a01.y, bd);
                    ffma2(acc[2][j], a23.x, bd);
                    ffma2(acc[3][j], a23.y, bd);
                }
            }
        }

        // scores + running argmin (mimic ref rounding: (xsq+esq) - 2*dot)
#pragma unroll
        for (int p = 0; p < 4; p++) {
#pragma unroll
            for (int j = 0; j < 8; j++) {
                float dlo, dhi;
                unpack_f32x2(acc[p][j], dlo, dhi);
                const int nl = tx * 8 + j;
                const int n  = ct + nl;
                const float eq = s_esq[nl];
                const float slo = (s_xsq[ty*8 + 2*p]     + eq) - 2.0f * dlo;
                const float shi = (s_xsq[ty*8 + 2*p + 1] + eq) - 2.0f * dhi;
                if (slo < best_s[2*p])     { best_s[2*p]     = slo; best_i[2*p]     = n; }
                if (shi < best_s[2*p + 1]) { best_s[2*p + 1] = shi; best_i[2*p + 1] = n; }
            }
        }
        __syncthreads();   // protect s_esq before next tile overwrite
    }

    // cross-thread argmin reduce (tie -> lowest index, matching jnp.argmin)
#pragma unroll
    for (int i = 0; i < 8; i++) {
        red_s[ty*8 + i][tx] = best_s[i];
        red_i[ty*8 + i][tx] = best_i[i];
    }
    __syncthreads();
    if (tid < BM) {
        float bs = red_s[tid][0];
        int   bi = red_i[tid][0];
#pragma unroll
        for (int t = 1; t < 16; t++) {
            const float s = red_s[tid][t];
            const int  ii = red_i[tid][t];
            if (s < bs || (s == bs && ii < bi)) { bs = s; bi = ii; }
        }
        const int row = row0 + tid;
        out[OFF_IND + row] = (float)bi;
        s_ind[tid] = bi;
        s_cl[tid] = bs;
        atomicAdd(&g_counts[bi], 1);
    }
    __syncthreads();
    if (tid == 0) {
        float t = 0.0f;
        for (int i = 0; i < BM; i++) t += s_cl[i];
        g_cl_part[blockIdx.x] = t;   // fixed slot -> deterministic
    }

    // fused gather + straight-through output for this block's 64 rows.
#pragma unroll
    for (int i = 0; i < 32; i++) {
        const int idx = i * 128 + tid;          // 4096 float4's = 64 rows x 64
        const int r  = idx >> 6;
        const int d  = (idx & 63) << 2;
        const int row = row0 + r;
        const float4 q = *reinterpret_cast<const float4*>(
            embedding + (size_t)s_ind[r] * D_DIM + d);
        const float4 x = *reinterpret_cast<const float4*>(
            latents + (size_t)row * D_DIM + d);
        float4 o;
        o.x = x.x + (q.x - x.x);   // fl(x + fl(q - x)) — matches ref STE expression
        o.y = x.y + (q.y - x.y);
        o.z = x.z + (q.z - x.z);
        o.w = x.w + (q.w - x.w);
        *reinterpret_cast<float4*>(out + (size_t)row * D_DIM + d) = o;
    }

    // ---- last-block-done: finalize scalars inside this launch ----
    __threadfence();
    if (tid == 0) s_last = (atomicAdd(&g_done, 1u) == 511u);
    __syncthreads();
    if (!s_last) return;

    __shared__ float sh[128];
    // sum of per-block min-dist partials (fixed order): vq_loss + cluster_metric
    float s = g_cl_part[tid] + g_cl_part[tid + 128]
            + g_cl_part[tid + 256] + g_cl_part[tid + 384];
    sh[tid] = s; __syncthreads();
#pragma unroll
    for (int o = 64; o; o >>= 1) { if (tid < o) sh[tid] += sh[tid + o]; __syncthreads(); }
    const float cl_sum = sh[0];
    __syncthreads();

    // entropy over code histogram
    s = 0.0f;
    for (int k = tid; k < K_CODES; k += 128) {
        const float p = (float)g_counts[k] * (1.0f / 32768.0f);
        s += p * logf(p + 1e-10f);
    }
    sh[tid] = s; __syncthreads();
#pragma unroll
    for (int o = 64; o; o >>= 1) { if (tid < o) sh[tid] += sh[tid + o]; __syncthreads(); }

    if (tid == 0) {
        const float m = cl_sum / 8388608.0f;         // mean((q-x)^2) over B*D
        out[OFF_VQ]  = m * 0.25f + m;                // beta*commitment + embedding loss
        out[OFF_ENT] = -sh[0];
        out[OFF_CL]  = cl_sum / 32768.0f;            // mean min-dist over B
    }
}

extern "C" void kernel_launch(void* const* d_in, const int* in_sizes, int n_in,
                              void* d_out, int out_size) {
    const float* latents   = (const float*)d_in[0];
    const float* embedding = (const float*)d_in[1];
    float* out = (float*)d_out;

    vq_prep_kernel<<<(B_ROWS + K_CODES) / 16, 256>>>(latents, embedding);
    vq_argmin_kernel<<<B_ROWS / BM, 128>>>(latents, embedding, out);
}